// round 8
// baseline (speedup 1.0000x reference)
#include <cuda_runtime.h>
#include <math.h>

#define B 8
#define C 64
#define L 2048
#define BCL (B*C*L)          // 1048576
#define NOUT (4*BCL)

// buffer slots in g_big
#define S_BUFA 0
#define S_BUFB 1
#define S_DET  2   // 3 buffers (lvl 1..3 coeffs; double as y state)
#define S_YIN  5   // 4
#define S_ACC  9   // 4
#define S_EVO  13  // 3
#define S_CURA 16
#define S_CURB 17
#define S_DMOD 18
#define NBUF   19

typedef unsigned long long ull;

// ---------------- device scratch (no allocation) ----------------
__device__ float g_big[(size_t)NBUF*BCL];
__device__ float g_W4s[11*4096*4];    // packed conv weights (float4 per (i,o))
__device__ float g_stat[512];
__device__ float g_lo[56], g_hi[56];
__device__ float g_ortho[1];
__device__ float g_ts[24];            // [lvl][5]
__device__ float g_rows[4*2048];
__device__ float g_modb[4*16*128];
__device__ float g_energy[64];
__device__ unsigned g_mm[8];

// ---------------- helpers ----------------
__device__ __forceinline__ float geluf(float x){ return 0.5f*x*(1.f+erff(x*0.70710678118654752f)); }
__device__ __forceinline__ float siluf(float x){ return x/(1.f+expf(-x)); }
__device__ __forceinline__ float sigmf(float x){ return 1.f/(1.f+expf(-x)); }

__device__ __forceinline__ ull pk2(float v){
    ull r; asm("mov.b64 %0,{%1,%1};" : "=l"(r) : "f"(v)); return r;
}
__device__ __forceinline__ ull mk2(float lo, float hi){
    ull r; asm("mov.b64 %0,{%1,%2};" : "=l"(r) : "f"(lo), "f"(hi)); return r;
}
__device__ __forceinline__ void upk(ull v, float& lo, float& hi){
    asm("mov.b64 {%0,%1},%2;" : "=f"(lo), "=f"(hi) : "l"(v));
}
__device__ __forceinline__ ull fma2(ull a, ull b, ull c){
    ull d; asm("fma.rn.f32x2 %0,%1,%2,%3;" : "=l"(d) : "l"(a), "l"(b), "l"(c)); return d;
}
// odd pair from two even pairs: (a.hi, b.lo)
__device__ __forceinline__ ull mkO(ull a, ull b){
    float alo, ahi, blo, bhi; upk(a, alo, ahi); upk(b, blo, bhi);
    return mk2(ahi, blo);
}

__device__ __forceinline__ size_t yboff(int lvl){
    return (lvl == 0) ? (size_t)S_BUFA*BCL : (size_t)(S_DET+lvl-1)*BCL;
}

// ---------------- pack conv weights [o][i][3] -> float4[i*64+o] ----------------
__global__ void k_pack(const float* __restrict__ c1, const float* __restrict__ c2,
                       const float* __restrict__ gw){
    int idx = blockIdx.x*256 + threadIdx.x;
    if (idx >= 11*4096) return;
    int slot = idx >> 12; int r = idx & 4095; int o = r >> 6; int i = r & 63;
    const float* src;
    if (slot < 4)      src = c1 + slot*12288;
    else if (slot < 8) src = c2 + (slot-4)*12288;
    else               src = gw + (slot-8)*12288;
    const float* w = src + (o*64 + i)*3;
    ((float4*)g_W4s)[slot*4096 + i*64 + o] = make_float4(w[0], w[1], w[2], 0.f);
}

// ---------------- stat: mean over L ----------------
__global__ void k_stat(const float* __restrict__ src){
    int r = blockIdx.x;
    const float* p = src + (size_t)r*L;
    float s = 0.f;
    for (int i = threadIdx.x; i < L; i += 256) s += p[i];
    __shared__ float red[256];
    red[threadIdx.x] = s; __syncthreads();
    for (int o = 128; o > 0; o >>= 1){
        if (threadIdx.x < o) red[threadIdx.x] += red[threadIdx.x+o];
        __syncthreads();
    }
    if (threadIdx.x == 0) g_stat[r] = red[0]*(1.f/(float)L);
}

// ---------------- dywan MLP + ortho (single block) ----------------
__global__ void k_mlp(const float* __restrict__ w1, const float* __restrict__ b1,
                      const float* __restrict__ wg1, const float* __restrict__ bg1,
                      const float* __restrict__ wg2, const float* __restrict__ bg2){
    __shared__ float ss[512], h1[512], h2[1024], sf[112];
    int tid = threadIdx.x;
    for (int i = tid; i < 512; i += 256) ss[i] = g_stat[i];
    __syncthreads();
    for (int idx = tid; idx < 512; idx += 256){
        int b = idx >> 6, j = idx & 63;
        float s = b1[j];
        const float* w = w1 + j*64; const float* st = ss + b*64;
        #pragma unroll 8
        for (int c = 0; c < 64; c++) s += w[c]*st[c];
        h1[idx] = geluf(s);
    }
    __syncthreads();
    for (int idx = tid; idx < 1024; idx += 256){
        int b = idx >> 7, j = idx & 127;
        float s = bg1[j];
        const float* w = wg1 + j*64; const float* hh = h1 + b*64;
        #pragma unroll 8
        for (int c = 0; c < 64; c++) s += w[c]*hh[c];
        h2[idx] = geluf(s);
    }
    __syncthreads();
    if (tid < 112){
        int b = tid/14, j = tid%14;
        float s = bg2[j];
        const float* w = wg2 + j*128; const float* hh = h2 + b*128;
        #pragma unroll 8
        for (int c = 0; c < 128; c++) s += w[c]*hh[c];
        sf[b*14+j] = s;
        if (j < 7) g_lo[b*7+j] = s; else g_hi[b*7+(j-7)] = s;
    }
    __syncthreads();
    if (tid == 0){
        float sm = 0.f;
        for (int b = 0; b < 8; b++){
            float prev = 0.f;
            for (int i = 0; i < 7; i++){ float v = sf[b*14+i]; sm += fabsf(v-prev); prev = v; }
            sm += fabsf(prev);
        }
        float lo_smooth = sm/64.f;
        float lon[8][7];
        for (int b = 0; b < 8; b++){
            float n = 0.f;
            for (int i = 0; i < 7; i++){ float v = sf[b*14+i]; n += v*v; }
            n = sqrtf(n) + 1e-8f;
            for (int i = 0; i < 7; i++) lon[b][i] = sf[b*14+i]/n;
        }
        float shift = 0.f;
        for (int s = 1; s <= 3; s++){
            float t = 0.f;
            for (int b = 0; b < 8; b++)
                for (int i = 0; i < 7; i++)
                    for (int jj = 0; jj < 7; jj++)
                        t += fabsf(lon[b][i]*lon[b][(jj - s + 7)%7]);
            shift += t/(8.f*49.f);
        }
        float amp = 0.f;
        for (int b = 0; b < 8; b++){
            float q = 0.f;
            for (int i = 0; i < 7; i++) q += lon[b][i]*lon[b][i];
            amp += fabsf(q - 1.f);
        }
        amp /= 8.f;
        g_ortho[0] = 0.01f*(shift+amp) + 0.1f*lo_smooth;
    }
}

// ---------------- per-batch 7-tap filter (edge pad), both filters ----------------
__global__ void k_filt(const float* __restrict__ src, float* __restrict__ na,
                       float* __restrict__ det){
    int idx = blockIdx.x*256 + threadIdx.x;
    if (idx >= BCL) return;
    int l = idx & (L-1);
    int bc = idx >> 11;
    int b = bc >> 6;
    const float* p = src + (size_t)bc*L;
    const float* flo = g_lo + b*7; const float* fhi = g_hi + b*7;
    float sa = 0.f, sd = 0.f;
    #pragma unroll
    for (int t = 0; t < 7; t++){
        int m = l + t - 3; m = m < 0 ? 0 : (m > L-1 ? L-1 : m);
        float v = p[m];
        sa += v*flo[t]; sd += v*fhi[t];
    }
    na[idx] = sa; det[idx] = sd;
}

__global__ void k_init(){
    int t = threadIdx.x;
    if (t < 4){ g_mm[t*2] = 0x7f7fffffu; g_mm[t*2+1] = 0u; }
}

// ---------------- adaptive time grid pass 1 (batched over 4 levels) ----------------
__global__ void k_grid1(){
    __shared__ float sd[2048];
    __shared__ float R[6][256];
    int lvl = blockIdx.x >> 9;
    int r = blockIdx.x & 511;
    const float* p = g_big + yboff(lvl) + (size_t)r*2048;
    int t = threadIdx.x;
    for (int i = t; i < 2048; i += 256) sd[i] = p[i];
    __syncthreads();
    float s1=0.f,s2=0.f,s3=0.f,s4=0.f, mn=3.4e38f, mx=0.f;
    for (int jj = t; jj < 2047; jj += 256){
        int lo = jj-2; if (lo < 0) lo = 0;
        int hi = jj+2; if (hi > 2046) hi = 2046;
        float g = 0.f;
        for (int q = lo; q <= hi; q++) g += fabsf(sd[q+1]-sd[q]);
        float inten = g*0.2f;
        mn = fminf(mn, inten); mx = fmaxf(mx, inten);
        if (jj < 511)  s1 += inten;
        if (jj < 1023) s2 += inten;
        if (jj < 1534) s3 += inten;
        if (jj < 2046) s4 += inten;
    }
    R[0][t]=s1; R[1][t]=s2; R[2][t]=s3; R[3][t]=s4; R[4][t]=mn; R[5][t]=mx;
    __syncthreads();
    for (int o = 128; o > 0; o >>= 1){
        if (t < o){
            R[0][t]+=R[0][t+o]; R[1][t]+=R[1][t+o]; R[2][t]+=R[2][t+o]; R[3][t]+=R[3][t+o];
            R[4][t]=fminf(R[4][t],R[4][t+o]); R[5][t]=fmaxf(R[5][t],R[5][t+o]);
        }
        __syncthreads();
    }
    if (t == 0){
        float* rows = g_rows + lvl*2048;
        rows[r*4+0]=R[0][0]; rows[r*4+1]=R[1][0]; rows[r*4+2]=R[2][0]; rows[r*4+3]=R[3][0];
        atomicMin(&g_mm[lvl*2+0], __float_as_uint(R[4][0]));
        atomicMax(&g_mm[lvl*2+1], __float_as_uint(R[5][0]));
    }
}

// ---------------- grid pass 2 (one block per level) ----------------
__global__ void k_grid2(){
    __shared__ float R[5][256];
    int lvl = blockIdx.x;
    float mn = __uint_as_float(g_mm[lvl*2+0]);
    float mx = __uint_as_float(g_mm[lvl*2+1]);
    float a, bb;
    if (mx - mn < 1e-8f){ a = 0.f; bb = 0.5f; }
    else { a = 0.9f/(mx - mn + 1e-30f); bb = 0.1f - a*mn; }
    int t = threadIdx.x;
    const float* rows = g_rows + lvl*2048;
    float p1=0.f,p2=0.f,p3=0.f,p4=0.f,m=-1.f;
    for (int r = t; r < 512; r += 256){
        float t1 = a*rows[r*4+0] + bb*511.f;
        float t2 = a*rows[r*4+1] + bb*1023.f;
        float t3 = a*rows[r*4+2] + bb*1534.f;
        float t4 = a*rows[r*4+3] + bb*2046.f;
        p1+=t1; p2+=t2; p3+=t3; p4+=t4; m = fmaxf(m, t4);
    }
    R[0][t]=p1; R[1][t]=p2; R[2][t]=p3; R[3][t]=p4; R[4][t]=m;
    __syncthreads();
    for (int o = 128; o > 0; o >>= 1){
        if (t < o){
            R[0][t]+=R[0][t+o]; R[1][t]+=R[1][t+o]; R[2][t]+=R[2][t+o]; R[3][t]+=R[3][t+o];
            R[4][t]=fmaxf(R[4][t],R[4][t+o]);
        }
        __syncthreads();
    }
    if (t == 0){
        float M = fmaxf(R[4][0], 1e-12f);
        float inv = 1.f/(512.f*M);
        float* ts = g_ts + lvl*5;
        ts[0]=0.f; ts[1]=R[0][0]*inv; ts[2]=R[1][0]*inv; ts[3]=R[2][0]*inv; ts[4]=R[3][0]*inv;
    }
}

// ---------------- modulation table (batched over levels) ----------------
__global__ void k_mod(const float* __restrict__ wt, const float* __restrict__ bt,
                      const float* __restrict__ wm, const float* __restrict__ bm,
                      const float* __restrict__ emb){
    int gid = blockIdx.x*256 + threadIdx.x;
    if (gid >= 8192) return;
    int lvl = gid >> 11; int rem = gid & 2047;
    int js = rem >> 7; int r = rem & 127;
    int j = js >> 2, s = js & 3;
    float t0 = g_ts[lvl*5+j], t1 = g_ts[lvl*5+j+1];
    float t = (s == 0) ? t0 : (s == 3 ? t1 : t0 + 0.5f*(t1-t0));
    float acc = bm[lvl*128 + r];
    #pragma unroll
    for (int k = 0; k < 16; k++){
        float te = siluf(wt[lvl*16+k]*t + bt[lvl*16+k]);
        acc = fmaf(wm[(lvl*128+r)*16+k], te, acc);
    }
    if (r < 64) g_modb[(lvl*16+js)*128 + r] = 1.f + acc + emb[(lvl*8+lvl)*64 + r];
    else        g_modb[(lvl*16+js)*128 + 64 + (r-64)] = acc;
}

// ---------------- energy: per (lvl,b) mean of squares ----------------
__global__ void k_energyB(int off){
    int lvl = blockIdx.x >> 3, b = blockIdx.x & 7;
    const float* p = g_big + yboff(lvl) + (size_t)b*131072;
    double s = 0.0;
    for (int i = threadIdx.x; i < 131072; i += 256){ float v = p[i]; s += (double)v*(double)v; }
    __shared__ double red[256];
    red[threadIdx.x] = s; __syncthreads();
    for (int o = 128; o > 0; o >>= 1){
        if (threadIdx.x < o) red[threadIdx.x] += red[threadIdx.x+o];
        __syncthreads();
    }
    if (threadIdx.x == 0) g_energy[off + lvl*8 + b] = (float)(red[0]/131072.0);
}

__global__ void k_scale(){
    int idx = blockIdx.x*256 + threadIdx.x;
    if (idx >= 4*(BCL/4)) return;
    int lvl = idx >> 18;
    int r = idx & (BCL/4 - 1);
    int b = r >> 15;
    float sc = sqrtf(g_energy[lvl*8+b]/(g_energy[32+lvl*8+b]+1e-8f));
    const float4* src = (const float4*)(g_big + yboff(lvl));
    float4* dst = (float4*)(g_big + ((lvl == 0) ? (size_t)S_CURA*BCL : (size_t)(S_EVO+lvl-1)*BCL));
    float4 v = src[r];
    v.x*=sc; v.y*=sc; v.z*=sc; v.w*=sc;
    dst[r] = v;
}

// ---------------- fused RK4 stage: 4-o register tiling, 128-col tiles ----------------
// grid (16 ltiles, 8 batch, 4 levels), 256 threads, smem 69120 B
// xs[64][136]: gl = l0-4+m (m 1..134 valid). E[p] = pair at m=2p.
// hs[64][134]: h col hc = l0-2+n. E_h[p] = pair at n=2p. hp range 0..65.
// hpair[hp] = w0*O[hp] + w1*E[hp+1] + w2*O[hp+1], O[p] = (E[p].hi, E[p+1].lo)
// outpair[op] = w0*Oh[op] + w1*Eh[op+1] + w2*Oh[op+1], op = 0..63
__global__ void __launch_bounds__(256,2)
k_stage(const float* __restrict__ c1b, const float* __restrict__ c2b, int j, int s)
{
    extern __shared__ float smem[];
    float* xs = smem;            // 64*136
    float* hs = smem + 8704;     // 64*134

    int lvl = blockIdx.z;
    int b   = blockIdx.y;
    int l0  = blockIdx.x*128;
    int tid = threadIdx.x;

    size_t ybo = yboff(lvl);
    size_t lvlbcl = (size_t)lvl*BCL;
    const float* cin = g_big + ((s==0) ? ybo : ((size_t)S_YIN*BCL + lvlbcl)) + (size_t)b*C*L;

    for (int idx = tid; idx < 8704; idx += 256){
        int row = idx/136, m = idx - row*136;
        int gl = l0 - 4 + m;
        xs[idx] = (m >= 1 && m <= 134 && gl >= 0 && gl < 2048) ? cin[row*2048 + gl] : 0.f;
    }
    __syncthreads();

    int oseg = tid >> 4, cseg = tid & 15;
    int o0 = oseg*4;
    bool xtra = (cseg < 2);
    int hpx = 64 + cseg;
    const float4* W1 = ((const float4*)g_W4s) + (size_t)lvl*4096;
    const float4* W2 = ((const float4*)g_W4s) + (size_t)(4+lvl)*4096;

    // ---- phase 1: conv1 -> h ----
    ull acc[4][4];      // [k][oo]
    ull accx[4];
    #pragma unroll
    for (int k = 0; k < 4; k++)
        #pragma unroll
        for (int oo = 0; oo < 4; oo++) acc[k][oo] = 0ull;
    #pragma unroll
    for (int oo = 0; oo < 4; oo++) accx[oo] = 0ull;
    {
        float4 wn0 = W1[o0], wn1 = W1[o0+1], wn2 = W1[o0+2], wn3 = W1[o0+3];
        for (int i = 0; i < 64; i++){
            float4 wa = wn0, wb = wn1, wc = wn2, wd = wn3;
            int ip = ((i+1)&63)<<6;
            wn0 = W1[ip+o0]; wn1 = W1[ip+o0+1]; wn2 = W1[ip+o0+2]; wn3 = W1[ip+o0+3];
            ull w0[4], w1[4], w2[4];
            w0[0]=pk2(wa.x); w1[0]=pk2(wa.y); w2[0]=pk2(wa.z);
            w0[1]=pk2(wb.x); w1[1]=pk2(wb.y); w2[1]=pk2(wb.z);
            w0[2]=pk2(wc.x); w1[2]=pk2(wc.y); w2[2]=pk2(wc.z);
            w0[3]=pk2(wd.x); w1[3]=pk2(wd.y); w2[3]=pk2(wd.z);
            const ull* A = (const ull*)(xs + i*136);
            #pragma unroll
            for (int k = 0; k < 4; k++){
                int hp = cseg + 16*k;
                ull E0 = A[hp], E1 = A[hp+1], E2 = A[hp+2];
                ull O0 = mkO(E0, E1), O1 = mkO(E1, E2);
                #pragma unroll
                for (int oo = 0; oo < 4; oo++){
                    acc[k][oo] = fma2(w0[oo], O0, acc[k][oo]);
                    acc[k][oo] = fma2(w1[oo], E1, acc[k][oo]);
                    acc[k][oo] = fma2(w2[oo], O1, acc[k][oo]);
                }
            }
            if (xtra){
                ull E0 = A[hpx], E1 = A[hpx+1], E2 = A[hpx+2];
                ull O0 = mkO(E0, E1), O1 = mkO(E1, E2);
                #pragma unroll
                for (int oo = 0; oo < 4; oo++){
                    accx[oo] = fma2(w0[oo], O0, accx[oo]);
                    accx[oo] = fma2(w1[oo], E1, accx[oo]);
                    accx[oo] = fma2(w2[oo], O1, accx[oo]);
                }
            }
        }
    }
    #pragma unroll
    for (int oo = 0; oo < 4; oo++){
        float b1v = c1b[lvl*64 + o0 + oo];
        #pragma unroll
        for (int k = 0; k < 4; k++){
            int hp = cseg + 16*k;
            int gc = l0 - 2 + 2*hp;
            float lo, hi; upk(acc[k][oo], lo, hi);
            float h0 = (gc   >= 0 && gc   < 2048) ? geluf(lo + b1v) : 0.f;
            float h1 = (gc+1 >= 0 && gc+1 < 2048) ? geluf(hi + b1v) : 0.f;
            *(ull*)(hs + (o0+oo)*134 + 2*hp) = mk2(h0, h1);
        }
        if (xtra){
            int gc = l0 - 2 + 2*hpx;
            float lo, hi; upk(accx[oo], lo, hi);
            float h0 = (gc   >= 0 && gc   < 2048) ? geluf(lo + b1v) : 0.f;
            float h1 = (gc+1 >= 0 && gc+1 < 2048) ? geluf(hi + b1v) : 0.f;
            *(ull*)(hs + (o0+oo)*134 + 2*hpx) = mk2(h0, h1);
        }
    }
    __syncthreads();

    // ---- phase 2: conv2 ----
    ull acc2[4][4];
    #pragma unroll
    for (int k = 0; k < 4; k++)
        #pragma unroll
        for (int oo = 0; oo < 4; oo++) acc2[k][oo] = 0ull;
    {
        float4 wn0 = W2[o0], wn1 = W2[o0+1], wn2 = W2[o0+2], wn3 = W2[o0+3];
        for (int i = 0; i < 64; i++){
            float4 wa = wn0, wb = wn1, wc = wn2, wd = wn3;
            int ip = ((i+1)&63)<<6;
            wn0 = W2[ip+o0]; wn1 = W2[ip+o0+1]; wn2 = W2[ip+o0+2]; wn3 = W2[ip+o0+3];
            ull w0[4], w1[4], w2[4];
            w0[0]=pk2(wa.x); w1[0]=pk2(wa.y); w2[0]=pk2(wa.z);
            w0[1]=pk2(wb.x); w1[1]=pk2(wb.y); w2[1]=pk2(wb.z);
            w0[2]=pk2(wc.x); w1[2]=pk2(wc.y); w2[2]=pk2(wc.z);
            w0[3]=pk2(wd.x); w1[3]=pk2(wd.y); w2[3]=pk2(wd.z);
            const ull* H = (const ull*)(hs + i*134);
            #pragma unroll
            for (int k = 0; k < 4; k++){
                int op = cseg + 16*k;
                ull E0 = H[op], E1 = H[op+1], E2 = H[op+2];
                ull O0 = mkO(E0, E1), O1 = mkO(E1, E2);
                #pragma unroll
                for (int oo = 0; oo < 4; oo++){
                    acc2[k][oo] = fma2(w0[oo], O0, acc2[k][oo]);
                    acc2[k][oo] = fma2(w1[oo], E1, acc2[k][oo]);
                    acc2[k][oo] = fma2(w2[oo], O1, acc2[k][oo]);
                }
            }
        }
    }

    // ---- epilogue: kv = silu(mod) - 0.1*y_stage ----
    float kv[4][4][2];
    {
        int msel = (lvl*16 + j*4 + s)*128;
        #pragma unroll
        for (int oo = 0; oo < 4; oo++){
            int o = o0 + oo;
            float m1p = g_modb[msel + o];
            float bet = g_modb[msel + 64 + o];
            float b2v = c2b[lvl*64 + o];
            #pragma unroll
            for (int k = 0; k < 4; k++){
                int col = 2*(cseg + 16*k);
                float lo, hi; upk(acc2[k][oo], lo, hi);
                kv[k][oo][0] = siluf((lo + b2v)*m1p + bet) - 0.1f*xs[o*136 + col + 4];
                kv[k][oo][1] = siluf((hi + b2v)*m1p + bet) - 0.1f*xs[o*136 + col + 5];
            }
        }
    }
    __syncthreads();
    #pragma unroll
    for (int k = 0; k < 4; k++){
        int col = 2*(cseg + 16*k);
        #pragma unroll
        for (int oo = 0; oo < 4; oo++)
            *(ull*)(hs + (o0+oo)*134 + col) = mk2(kv[k][oo][0], kv[k][oo][1]);
    }
    __syncthreads();

    float dt  = g_ts[lvl*5 + j + 1] - g_ts[lvl*5 + j];
    float c_acc = (s == 0 || s == 3) ? dt*(1.f/6.f) : dt*(1.f/3.f);
    float c_y   = (s == 2) ? dt : dt*0.5f;
    for (int idx = tid; idx < 8192; idx += 256){
        int o2 = idx >> 7, q = idx & 127;
        float kvv = hs[o2*134 + q];
        size_t g = ((size_t)b*64 + o2)*2048 + l0 + q;
        if (s == 0){
            float yvv = g_big[ybo + g];
            g_big[(size_t)S_ACC*BCL + lvlbcl + g] = yvv + c_acc*kvv;
            g_big[(size_t)S_YIN*BCL + lvlbcl + g] = yvv + c_y*kvv;
        } else if (s < 3){
            float yvv = g_big[ybo + g];
            g_big[(size_t)S_ACC*BCL + lvlbcl + g] += c_acc*kvv;
            g_big[(size_t)S_YIN*BCL + lvlbcl + g] = yvv + c_y*kvv;
        } else {
            g_big[ybo + g] = g_big[(size_t)S_ACC*BCL + lvlbcl + g] + c_acc*kvv;
        }
    }
}

// ---------------- recon gate conv (packed core): dst = cur + sigmoid(conv(cur)+gb)*det ----
// grid (32 ltiles, 8 batch), 256 threads. smem: xs 4608 + xso 4608 + ds 64*66
__global__ void __launch_bounds__(256,3)
k_gate(const float* __restrict__ cur, int wslot, const float* __restrict__ gb,
       const float* __restrict__ det, float* __restrict__ dstcur,
       float* __restrict__ outdet)
{
    extern __shared__ float smem[];
    float* xs  = smem;            // 64*72, gl = l0-3+m
    float* xso = smem + 4608;
    float* ds  = smem + 9216;     // 64*66 (stride 66)

    int b  = blockIdx.y;
    int l0 = blockIdx.x*64;
    int tid = threadIdx.x;
    const float* cb = cur + (size_t)b*C*L;

    for (int idx = tid; idx < 4608; idx += 256){
        int row = idx/72, m = idx - row*72;
        int gl = l0 - 3 + m;
        float v = (m < 70 && gl >= 0 && gl < 2048) ? cb[row*2048 + gl] : 0.f;
        xs[idx] = v;
        if (m > 0) xso[row*72 + m - 1] = v;
        else       xso[row*72 + 71] = 0.f;
    }
    for (int idx = tid; idx < 4096; idx += 256){
        int row = idx >> 6, q = idx & 63;
        ds[row*66 + q] = det[((size_t)b*64 + row)*2048 + l0 + q];
    }
    __syncthreads();

    int o = tid & 63, seg = tid >> 6;
    int k0 = seg*8;
    const float4* W = ((const float4*)g_W4s) + (size_t)wslot*4096;
    ull acc[8];
    #pragma unroll
    for (int k = 0; k < 8; k++) acc[k] = 0ull;
    {
        float4 wnext = W[o];
        for (int i = 0; i < 64; i++){
            float4 wv = wnext;
            wnext = W[(((i+1)&63)<<6) + o];
            ull w0 = pk2(wv.x), w1 = pk2(wv.y), w2 = pk2(wv.z);
            const ull* A = (const ull*)(xs  + i*72) + (k0 + 1);
            const ull* O = (const ull*)(xso + i*72) + (k0 + 1);
            ull Ep = A[0];
            #pragma unroll
            for (int k = 0; k < 8; k++){
                ull En = A[k+1];
                ull Ok = O[k];
                acc[k] = fma2(w0, Ep, acc[k]);
                acc[k] = fma2(w1, Ok, acc[k]);
                acc[k] = fma2(w2, En, acc[k]);
                Ep = En;
            }
        }
    }
    {
        float gbv = gb[o];
        size_t rowbase = ((size_t)b*64 + o)*2048 + l0;
        #pragma unroll
        for (int k = 0; k < 8; k++){
            int jq = 2*(k0 + k);
            float lo, hi; upk(acc[k], lo, hi);
            float g0 = sigmf(lo + gbv), g1 = sigmf(hi + gbv);
            float cv0 = xs[o*72 + jq + 3];
            float cv1 = xs[o*72 + jq + 4];
            float d0 = ds[o*66 + jq];
            float d1 = ds[o*66 + jq + 1];
            *(ull*)(dstcur + rowbase + jq) = mk2(cv0 + g0*d0, cv1 + g1*d1);
        }
    }
    if (outdet){
        for (int idx = tid; idx < 4096; idx += 256){
            int row = idx >> 6, q = idx & 63;
            outdet[((size_t)b*64 + row)*2048 + l0 + q] = ds[row*66 + q];
        }
    }
}

// ---------------- 1x1 attention (C->16->C) + detail modulation ----------------
__global__ void k_attn(const float* __restrict__ cur,
                       const float* __restrict__ w1, const float* __restrict__ b1,
                       const float* __restrict__ w2, const float* __restrict__ b2,
                       const float* __restrict__ det, float* __restrict__ dmod,
                       float* __restrict__ outdet){
    __shared__ float sm[128*65];
    int b = blockIdx.y, l0 = blockIdx.x*128;
    int tid = threadIdx.x;
    for (int idx = tid; idx < 64*128; idx += 128){
        int c = idx >> 7, l = idx & 127;
        sm[l*65 + c] = cur[((size_t)b*64+c)*2048 + l0 + l];
    }
    __syncthreads();
    int l = tid;
    float h16[16];
    #pragma unroll
    for (int k = 0; k < 16; k++){
        float a = b1[k];
        const float* wr = w1 + k*64;
        #pragma unroll 8
        for (int c = 0; c < 64; c++) a += wr[c]*sm[l*65+c];
        h16[k] = geluf(a);
    }
    for (int c = 0; c < 64; c++){
        float a = b2[c];
        const float* wr = w2 + c*16;
        #pragma unroll
        for (int k = 0; k < 16; k++) a += wr[k]*h16[k];
        a = sigmf(a);
        size_t id = ((size_t)b*64+c)*2048 + l0 + l;
        float dv = det[id]*(1.f + a);
        dmod[id] = dv;
        outdet[id] = dv;
    }
}

__global__ void k_tail(float* out){ out[NOUT] = g_ortho[0]; }

// ---------------- host ----------------
extern "C" void kernel_launch(void* const* d_in, const int* in_sizes, int n_in,
                              void* d_out, int out_size) {
    const float* x      = (const float*)d_in[0];
    const float* dy_w1  = (const float*)d_in[1];
    const float* dy_b1  = (const float*)d_in[2];
    const float* dy_wg1 = (const float*)d_in[3];
    const float* dy_bg1 = (const float*)d_in[4];
    const float* dy_wg2 = (const float*)d_in[5];
    const float* dy_bg2 = (const float*)d_in[6];
    const float* c1w    = (const float*)d_in[7];
    const float* c1b    = (const float*)d_in[8];
    const float* c2w    = (const float*)d_in[9];
    const float* c2b    = (const float*)d_in[10];
    const float* wt     = (const float*)d_in[11];
    const float* bt     = (const float*)d_in[12];
    const float* wm     = (const float*)d_in[13];
    const float* bm     = (const float*)d_in[14];
    const float* emb    = (const float*)d_in[15];
    const float* gate_w = (const float*)d_in[16];
    const float* gate_b = (const float*)d_in[17];
    const float* a1w    = (const float*)d_in[18];
    const float* a1b    = (const float*)d_in[19];
    const float* a2w    = (const float*)d_in[20];
    const float* a2b    = (const float*)d_in[21];
    float* out = (float*)d_out;

    cudaFuncSetAttribute(k_stage, cudaFuncAttributeMaxDynamicSharedMemorySize, 69120);
    cudaFuncSetAttribute(k_gate,  cudaFuncAttributeMaxDynamicSharedMemorySize, 53760);

    void* pbig = nullptr; cudaGetSymbolAddress(&pbig, g_big);
    float* big = (float*)pbig;

    float* bufA = big + (size_t)S_BUFA*BCL;
    float* bufB = big + (size_t)S_BUFB*BCL;
    float* detb = big + (size_t)S_DET*BCL;
    float* evob = big + (size_t)S_EVO*BCL;
    float* curA = big + (size_t)S_CURA*BCL;
    float* curB = big + (size_t)S_CURB*BCL;
    float* dmod = big + (size_t)S_DMOD*BCL;

    k_pack<<<176,256>>>(c1w, c2w, gate_w);

    // ---- decomposition (3 levels); final approx lands in bufA ----
    const float* aps[3] = { x, bufA, bufB };
    float* naps[3] = { bufA, bufB, bufA };
    for (int lev = 0; lev < 3; lev++){
        k_stat<<<512,256>>>(aps[lev]);
        k_mlp<<<1,256>>>(dy_w1, dy_b1, dy_wg1, dy_bg1, dy_wg2, dy_bg2);
        k_filt<<<4096,256>>>(aps[lev], naps[lev], detb + (size_t)lev*BCL);
    }

    // ---- ODE prep for all 4 levels ----
    k_init<<<1,32>>>();
    k_grid1<<<2048,256>>>();
    k_grid2<<<4,256>>>();
    k_mod<<<32,256>>>(wt, bt, wm, bm, emb);
    k_energyB<<<32,256>>>(0);

    // ---- RK4: 16 fused stages, all levels concurrently ----
    dim3 sgrid(16, 8, 4);
    for (int j = 0; j < 4; j++)
        for (int s = 0; s < 4; s++)
            k_stage<<<sgrid, 256, 69120>>>(c1b, c2b, j, s);

    k_energyB<<<32,256>>>(32);
    k_scale<<<4096,256>>>();

    // ---- reconstruction ----
    dim3 ggrid(32, 8);
    dim3 agrid(16, 8);
    k_gate<<<ggrid,256,53760>>>(curA, 10, gate_b + 128,
                                evob + (size_t)2*BCL, curB, out + (size_t)3*BCL);
    k_attn<<<agrid,128>>>(curB, a1w + 1024, a1b + 16, a2w + 1024, a2b + 64,
                          evob + (size_t)1*BCL, dmod, out + (size_t)2*BCL);
    k_gate<<<ggrid,256,53760>>>(curB, 9, gate_b + 64, dmod, curA, nullptr);
    k_attn<<<agrid,128>>>(curA, a1w, a1b, a2w, a2b,
                          evob, dmod, out + (size_t)1*BCL);
    k_gate<<<ggrid,256,53760>>>(curA, 8, gate_b, dmod, out, nullptr);

    if (out_size > NOUT) k_tail<<<1,1>>>(out);
}

// round 11
// speedup vs baseline: 1.1978x; 1.1978x over previous
#include <cuda_runtime.h>
#include <math.h>

#define B 8
#define C 64
#define L 2048
#define BCL (B*C*L)          // 1048576
#define NOUT (4*BCL)

// buffer slots in g_big
#define S_BUFA 0
#define S_BUFB 1
#define S_DET  2   // 3 buffers (lvl 1..3 coeffs; double as y state)
#define S_YIN  5   // 4
#define S_ACC  9   // 4
#define S_EVO  13  // 3
#define S_CURA 16
#define S_CURB 17
#define S_DMOD 18
#define NBUF   19

typedef unsigned long long ull;

// ---------------- device scratch (no allocation) ----------------
__device__ float g_big[(size_t)NBUF*BCL];
__device__ float g_W4s[11*4096*4];    // packed conv weights (float4 per (i,o))
__device__ float g_stat[512];
__device__ float g_lo[56], g_hi[56];
__device__ float g_ortho[1];
__device__ float g_ts[24];            // [lvl][5]
__device__ float g_rows[4*2048];
__device__ float g_modb[4*16*128];
__device__ float g_energy[64];
__device__ unsigned g_mm[8];

// ---------------- helpers ----------------
__device__ __forceinline__ float geluf(float x){ return 0.5f*x*(1.f+erff(x*0.70710678118654752f)); }
__device__ __forceinline__ float siluf(float x){ return x/(1.f+expf(-x)); }
__device__ __forceinline__ float sigmf(float x){ return 1.f/(1.f+expf(-x)); }

__device__ __forceinline__ ull pk2(float v){
    ull r; asm("mov.b64 %0,{%1,%1};" : "=l"(r) : "f"(v)); return r;
}
__device__ __forceinline__ ull mk2(float lo, float hi){
    ull r; asm("mov.b64 %0,{%1,%2};" : "=l"(r) : "f"(lo), "f"(hi)); return r;
}
__device__ __forceinline__ void upk(ull v, float& lo, float& hi){
    asm("mov.b64 {%0,%1},%2;" : "=f"(lo), "=f"(hi) : "l"(v));
}
__device__ __forceinline__ ull fma2(ull a, ull b, ull c){
    ull d; asm("fma.rn.f32x2 %0,%1,%2,%3;" : "=l"(d) : "l"(a), "l"(b), "l"(c)); return d;
}
// odd pair from two even pairs: (a.hi, b.lo)
__device__ __forceinline__ ull mkO(ull a, ull b){
    float alo, ahi, blo, bhi; upk(a, alo, ahi); upk(b, blo, bhi);
    return mk2(ahi, blo);
}

__device__ __forceinline__ size_t yboff(int lvl){
    return (lvl == 0) ? (size_t)S_BUFA*BCL : (size_t)(S_DET+lvl-1)*BCL;
}

// ---------------- pack conv weights [o][i][3] -> float4[i*64+o] ----------------
__global__ void k_pack(const float* __restrict__ c1, const float* __restrict__ c2,
                       const float* __restrict__ gw){
    int idx = blockIdx.x*256 + threadIdx.x;
    if (idx >= 11*4096) return;
    int slot = idx >> 12; int r = idx & 4095; int o = r >> 6; int i = r & 63;
    const float* src;
    if (slot < 4)      src = c1 + slot*12288;
    else if (slot < 8) src = c2 + (slot-4)*12288;
    else               src = gw + (slot-8)*12288;
    const float* w = src + (o*64 + i)*3;
    ((float4*)g_W4s)[slot*4096 + i*64 + o] = make_float4(w[0], w[1], w[2], 0.f);
}

// ---------------- stat: mean over L ----------------
__global__ void k_stat(const float* __restrict__ src){
    int r = blockIdx.x;
    const float* p = src + (size_t)r*L;
    float s = 0.f;
    for (int i = threadIdx.x; i < L; i += 256) s += p[i];
    __shared__ float red[256];
    red[threadIdx.x] = s; __syncthreads();
    for (int o = 128; o > 0; o >>= 1){
        if (threadIdx.x < o) red[threadIdx.x] += red[threadIdx.x+o];
        __syncthreads();
    }
    if (threadIdx.x == 0) g_stat[r] = red[0]*(1.f/(float)L);
}

// ---------------- dywan MLP + ortho (single block) ----------------
__global__ void k_mlp(const float* __restrict__ w1, const float* __restrict__ b1,
                      const float* __restrict__ wg1, const float* __restrict__ bg1,
                      const float* __restrict__ wg2, const float* __restrict__ bg2){
    __shared__ float ss[512], h1[512], h2[1024], sf[112];
    int tid = threadIdx.x;
    for (int i = tid; i < 512; i += 256) ss[i] = g_stat[i];
    __syncthreads();
    for (int idx = tid; idx < 512; idx += 256){
        int b = idx >> 6, j = idx & 63;
        float s = b1[j];
        const float* w = w1 + j*64; const float* st = ss + b*64;
        #pragma unroll 8
        for (int c = 0; c < 64; c++) s += w[c]*st[c];
        h1[idx] = geluf(s);
    }
    __syncthreads();
    for (int idx = tid; idx < 1024; idx += 256){
        int b = idx >> 7, j = idx & 127;
        float s = bg1[j];
        const float* w = wg1 + j*64; const float* hh = h1 + b*64;
        #pragma unroll 8
        for (int c = 0; c < 64; c++) s += w[c]*hh[c];
        h2[idx] = geluf(s);
    }
    __syncthreads();
    if (tid < 112){
        int b = tid/14, j = tid%14;
        float s = bg2[j];
        const float* w = wg2 + j*128; const float* hh = h2 + b*128;
        #pragma unroll 8
        for (int c = 0; c < 128; c++) s += w[c]*hh[c];
        sf[b*14+j] = s;
        if (j < 7) g_lo[b*7+j] = s; else g_hi[b*7+(j-7)] = s;
    }
    __syncthreads();
    if (tid == 0){
        float sm = 0.f;
        for (int b = 0; b < 8; b++){
            float prev = 0.f;
            for (int i = 0; i < 7; i++){ float v = sf[b*14+i]; sm += fabsf(v-prev); prev = v; }
            sm += fabsf(prev);
        }
        float lo_smooth = sm/64.f;
        float lon[8][7];
        for (int b = 0; b < 8; b++){
            float n = 0.f;
            for (int i = 0; i < 7; i++){ float v = sf[b*14+i]; n += v*v; }
            n = sqrtf(n) + 1e-8f;
            for (int i = 0; i < 7; i++) lon[b][i] = sf[b*14+i]/n;
        }
        float shift = 0.f;
        for (int s = 1; s <= 3; s++){
            float t = 0.f;
            for (int b = 0; b < 8; b++)
                for (int i = 0; i < 7; i++)
                    for (int jj = 0; jj < 7; jj++)
                        t += fabsf(lon[b][i]*lon[b][(jj - s + 7)%7]);
            shift += t/(8.f*49.f);
        }
        float amp = 0.f;
        for (int b = 0; b < 8; b++){
            float q = 0.f;
            for (int i = 0; i < 7; i++) q += lon[b][i]*lon[b][i];
            amp += fabsf(q - 1.f);
        }
        amp /= 8.f;
        g_ortho[0] = 0.01f*(shift+amp) + 0.1f*lo_smooth;
    }
}

// ---------------- per-batch 7-tap filter (edge pad), both filters ----------------
__global__ void k_filt(const float* __restrict__ src, float* __restrict__ na,
                       float* __restrict__ det){
    int idx = blockIdx.x*256 + threadIdx.x;
    if (idx >= BCL) return;
    int l = idx & (L-1);
    int bc = idx >> 11;
    int b = bc >> 6;
    const float* p = src + (size_t)bc*L;
    const float* flo = g_lo + b*7; const float* fhi = g_hi + b*7;
    float sa = 0.f, sd = 0.f;
    #pragma unroll
    for (int t = 0; t < 7; t++){
        int m = l + t - 3; m = m < 0 ? 0 : (m > L-1 ? L-1 : m);
        float v = p[m];
        sa += v*flo[t]; sd += v*fhi[t];
    }
    na[idx] = sa; det[idx] = sd;
}

__global__ void k_init(){
    int t = threadIdx.x;
    if (t < 4){ g_mm[t*2] = 0x7f7fffffu; g_mm[t*2+1] = 0u; }
}

// ---------------- adaptive time grid pass 1 (batched over 4 levels) ----------------
__global__ void k_grid1(){
    __shared__ float sd[2048];
    __shared__ float R[6][256];
    int lvl = blockIdx.x >> 9;
    int r = blockIdx.x & 511;
    const float* p = g_big + yboff(lvl) + (size_t)r*2048;
    int t = threadIdx.x;
    for (int i = t; i < 2048; i += 256) sd[i] = p[i];
    __syncthreads();
    float s1=0.f,s2=0.f,s3=0.f,s4=0.f, mn=3.4e38f, mx=0.f;
    for (int jj = t; jj < 2047; jj += 256){
        int lo = jj-2; if (lo < 0) lo = 0;
        int hi = jj+2; if (hi > 2046) hi = 2046;
        float g = 0.f;
        for (int q = lo; q <= hi; q++) g += fabsf(sd[q+1]-sd[q]);
        float inten = g*0.2f;
        mn = fminf(mn, inten); mx = fmaxf(mx, inten);
        if (jj < 511)  s1 += inten;
        if (jj < 1023) s2 += inten;
        if (jj < 1534) s3 += inten;
        if (jj < 2046) s4 += inten;
    }
    R[0][t]=s1; R[1][t]=s2; R[2][t]=s3; R[3][t]=s4; R[4][t]=mn; R[5][t]=mx;
    __syncthreads();
    for (int o = 128; o > 0; o >>= 1){
        if (t < o){
            R[0][t]+=R[0][t+o]; R[1][t]+=R[1][t+o]; R[2][t]+=R[2][t+o]; R[3][t]+=R[3][t+o];
            R[4][t]=fminf(R[4][t],R[4][t+o]); R[5][t]=fmaxf(R[5][t],R[5][t+o]);
        }
        __syncthreads();
    }
    if (t == 0){
        float* rows = g_rows + lvl*2048;
        rows[r*4+0]=R[0][0]; rows[r*4+1]=R[1][0]; rows[r*4+2]=R[2][0]; rows[r*4+3]=R[3][0];
        atomicMin(&g_mm[lvl*2+0], __float_as_uint(R[4][0]));
        atomicMax(&g_mm[lvl*2+1], __float_as_uint(R[5][0]));
    }
}

// ---------------- grid pass 2 (one block per level) ----------------
__global__ void k_grid2(){
    __shared__ float R[5][256];
    int lvl = blockIdx.x;
    float mn = __uint_as_float(g_mm[lvl*2+0]);
    float mx = __uint_as_float(g_mm[lvl*2+1]);
    float a, bb;
    if (mx - mn < 1e-8f){ a = 0.f; bb = 0.5f; }
    else { a = 0.9f/(mx - mn + 1e-30f); bb = 0.1f - a*mn; }
    int t = threadIdx.x;
    const float* rows = g_rows + lvl*2048;
    float p1=0.f,p2=0.f,p3=0.f,p4=0.f,m=-1.f;
    for (int r = t; r < 512; r += 256){
        float t1 = a*rows[r*4+0] + bb*511.f;
        float t2 = a*rows[r*4+1] + bb*1023.f;
        float t3 = a*rows[r*4+2] + bb*1534.f;
        float t4 = a*rows[r*4+3] + bb*2046.f;
        p1+=t1; p2+=t2; p3+=t3; p4+=t4; m = fmaxf(m, t4);
    }
    R[0][t]=p1; R[1][t]=p2; R[2][t]=p3; R[3][t]=p4; R[4][t]=m;
    __syncthreads();
    for (int o = 128; o > 0; o >>= 1){
        if (t < o){
            R[0][t]+=R[0][t+o]; R[1][t]+=R[1][t+o]; R[2][t]+=R[2][t+o]; R[3][t]+=R[3][t+o];
            R[4][t]=fmaxf(R[4][t],R[4][t+o]);
        }
        __syncthreads();
    }
    if (t == 0){
        float M = fmaxf(R[4][0], 1e-12f);
        float inv = 1.f/(512.f*M);
        float* ts = g_ts + lvl*5;
        ts[0]=0.f; ts[1]=R[0][0]*inv; ts[2]=R[1][0]*inv; ts[3]=R[2][0]*inv; ts[4]=R[3][0]*inv;
    }
}

// ---------------- modulation table (batched over levels) ----------------
__global__ void k_mod(const float* __restrict__ wt, const float* __restrict__ bt,
                      const float* __restrict__ wm, const float* __restrict__ bm,
                      const float* __restrict__ emb){
    int gid = blockIdx.x*256 + threadIdx.x;
    if (gid >= 8192) return;
    int lvl = gid >> 11; int rem = gid & 2047;
    int js = rem >> 7; int r = rem & 127;
    int j = js >> 2, s = js & 3;
    float t0 = g_ts[lvl*5+j], t1 = g_ts[lvl*5+j+1];
    float t = (s == 0) ? t0 : (s == 3 ? t1 : t0 + 0.5f*(t1-t0));
    float acc = bm[lvl*128 + r];
    #pragma unroll
    for (int k = 0; k < 16; k++){
        float te = siluf(wt[lvl*16+k]*t + bt[lvl*16+k]);
        acc = fmaf(wm[(lvl*128+r)*16+k], te, acc);
    }
    if (r < 64) g_modb[(lvl*16+js)*128 + r] = 1.f + acc + emb[(lvl*8+lvl)*64 + r];
    else        g_modb[(lvl*16+js)*128 + 64 + (r-64)] = acc;
}

// ---------------- energy: per (lvl,b) mean of squares ----------------
__global__ void k_energyB(int off){
    int lvl = blockIdx.x >> 3, b = blockIdx.x & 7;
    const float* p = g_big + yboff(lvl) + (size_t)b*131072;
    double s = 0.0;
    for (int i = threadIdx.x; i < 131072; i += 256){ float v = p[i]; s += (double)v*(double)v; }
    __shared__ double red[256];
    red[threadIdx.x] = s; __syncthreads();
    for (int o = 128; o > 0; o >>= 1){
        if (threadIdx.x < o) red[threadIdx.x] += red[threadIdx.x+o];
        __syncthreads();
    }
    if (threadIdx.x == 0) g_energy[off + lvl*8 + b] = (float)(red[0]/131072.0);
}

__global__ void k_scale(){
    int idx = blockIdx.x*256 + threadIdx.x;
    if (idx >= 4*(BCL/4)) return;
    int lvl = idx >> 18;
    int r = idx & (BCL/4 - 1);
    int b = r >> 15;
    float sc = sqrtf(g_energy[lvl*8+b]/(g_energy[32+lvl*8+b]+1e-8f));
    const float4* src = (const float4*)(g_big + yboff(lvl));
    float4* dst = (float4*)(g_big + ((lvl == 0) ? (size_t)S_CURA*BCL : (size_t)(S_EVO+lvl-1)*BCL));
    float4 v = src[r];
    v.x*=sc; v.y*=sc; v.z*=sc; v.w*=sc;
    dst[r] = v;
}

// ---------------- fused RK4 stage (lean core, no shadow arrays, 4 CTAs/SM) ----------------
// grid (32 ltiles(64 cols), 8 batch, 4 levels), 256 threads
// smem: xs 64x72 (cols gl=l0-3+m, m<70 valid), hs 64x74 (cols ghl=l0-2+hc). 37376 B.
__global__ void __launch_bounds__(256,4)
k_stage(const float* __restrict__ c1b, const float* __restrict__ c2b, int j, int s)
{
    extern __shared__ float smem[];
    float* xs = smem;            // 64*72
    float* hs = smem + 4608;     // 64*74

    int lvl = blockIdx.z;
    int b   = blockIdx.y;
    int l0  = blockIdx.x*64;
    int tid = threadIdx.x;

    size_t ybo = yboff(lvl);
    size_t lvlbcl = (size_t)lvl*BCL;
    const float* cin = g_big + ((s==0) ? ybo : ((size_t)S_YIN*BCL + lvlbcl)) + (size_t)b*C*L;

    for (int idx = tid; idx < 4608; idx += 256){
        int row = idx/72, m = idx - row*72;
        int gl = l0 - 3 + m;
        xs[idx] = (m < 70 && gl >= 0 && gl < 2048) ? cin[row*2048 + gl] : 0.f;
    }
    __syncthreads();

    int o = tid & 63, seg = tid >> 6;
    const float4* W1 = ((const float4*)g_W4s) + (size_t)lvl*4096;
    const float4* W2 = ((const float4*)g_W4s) + (size_t)(4+lvl)*4096;

    // ---- phase 1: conv1 -> h pairs p = seg*9 .. seg*9+8 ----
    // Hpair[p] = w0*E[p] + w1*O[p] + w2*E[p+1];  O[p] = (E[p].hi, E[p+1].lo)
    int p0 = seg*9;
    ull acc1[9];
    #pragma unroll
    for (int k = 0; k < 9; k++) acc1[k] = 0ull;
    {
        float4 wnext = W1[o];
        for (int i = 0; i < 64; i++){
            float4 wv = wnext;
            wnext = W1[(((i+1)&63)<<6) + o];
            ull w0 = pk2(wv.x), w1 = pk2(wv.y), w2 = pk2(wv.z);
            const ull* A = (const ull*)(xs + i*72) + p0;
            ull Ep = A[0];
            #pragma unroll
            for (int k = 0; k < 9; k++){
                ull En = A[k+1];
                ull Ok = mkO(Ep, En);
                acc1[k] = fma2(w0, Ep, acc1[k]);
                acc1[k] = fma2(w1, Ok, acc1[k]);
                acc1[k] = fma2(w2, En, acc1[k]);
                Ep = En;
            }
        }
    }
    {
        float b1v = c1b[lvl*64 + o];
        #pragma unroll
        for (int k = 0; k < 9; k++){
            int p = p0 + k;
            int g0 = l0 - 2 + 2*p;
            float lo, hi; upk(acc1[k], lo, hi);
            float h0 = (g0   >= 0 && g0   < 2048) ? geluf(lo + b1v) : 0.f;
            float h1 = (g0+1 >= 0 && g0+1 < 2048) ? geluf(hi + b1v) : 0.f;
            *(ull*)(hs + o*74 + 2*p) = mk2(h0, h1);
        }
    }
    __syncthreads();

    // ---- phase 2: conv2, out pairs op = seg*8 .. seg*8+7 ----
    // OutPair[op] = w0*HO[op] + w1*HE[op+1] + w2*HO[op+1];  HO[p] = (HE[p].hi, HE[p+1].lo)
    int op0 = seg*8;
    ull acc2[8];
    #pragma unroll
    for (int k = 0; k < 8; k++) acc2[k] = 0ull;
    {
        float4 wnext = W2[o];
        for (int i = 0; i < 64; i++){
            float4 wv = wnext;
            wnext = W2[(((i+1)&63)<<6) + o];
            ull w0 = pk2(wv.x), w1 = pk2(wv.y), w2 = pk2(wv.z);
            const ull* H = (const ull*)(hs + i*74) + op0;
            ull E1 = H[0];
            ull E2 = H[1];
            ull Op = mkO(E1, E2);
            E1 = E2;
            #pragma unroll
            for (int k = 0; k < 8; k++){
                ull En = H[k+2];
                ull On = mkO(E1, En);
                acc2[k] = fma2(w0, Op, acc2[k]);
                acc2[k] = fma2(w1, E1, acc2[k]);
                acc2[k] = fma2(w2, On, acc2[k]);
                Op = On; E1 = En;
            }
        }
    }

    // ---- epilogue: kv = silu(mod) - 0.1*y_stage ----
    float kv[8][2];
    {
        int msel = (lvl*16 + j*4 + s)*128;
        float m1p = g_modb[msel + o];
        float bet = g_modb[msel + 64 + o];
        float b2v = c2b[lvl*64 + o];
        #pragma unroll
        for (int k = 0; k < 8; k++){
            int col = 2*(op0 + k);
            float lo, hi; upk(acc2[k], lo, hi);
            kv[k][0] = siluf((lo + b2v)*m1p + bet) - 0.1f*xs[o*72 + col + 3];
            kv[k][1] = siluf((hi + b2v)*m1p + bet) - 0.1f*xs[o*72 + col + 4];
        }
    }
    __syncthreads();
    #pragma unroll
    for (int k = 0; k < 8; k++){
        int col = 2*(op0 + k);
        *(ull*)(hs + o*74 + col) = mk2(kv[k][0], kv[k][1]);
    }
    __syncthreads();

    float dt  = g_ts[lvl*5 + j + 1] - g_ts[lvl*5 + j];
    float c_acc = (s == 0 || s == 3) ? dt*(1.f/6.f) : dt*(1.f/3.f);
    float c_y   = (s == 2) ? dt : dt*0.5f;
    for (int idx = tid; idx < 4096; idx += 256){
        int o2 = idx >> 6, q = idx & 63;
        float kvv = hs[o2*74 + q];
        size_t g = ((size_t)b*64 + o2)*2048 + l0 + q;
        if (s == 0){
            float yvv = g_big[ybo + g];
            g_big[(size_t)S_ACC*BCL + lvlbcl + g] = yvv + c_acc*kvv;
            g_big[(size_t)S_YIN*BCL + lvlbcl + g] = yvv + c_y*kvv;
        } else if (s < 3){
            float yvv = g_big[ybo + g];
            g_big[(size_t)S_ACC*BCL + lvlbcl + g] += c_acc*kvv;
            g_big[(size_t)S_YIN*BCL + lvlbcl + g] = yvv + c_y*kvv;
        } else {
            g_big[ybo + g] = g_big[(size_t)S_ACC*BCL + lvlbcl + g] + c_acc*kvv;
        }
    }
}

// ---------------- recon gate conv (packed core): dst = cur + sigmoid(conv(cur)+gb)*det ----
// grid (32 ltiles, 8 batch), 256 threads. smem: xs 4608 + xso 4608 + ds 64*66
__global__ void __launch_bounds__(256,3)
k_gate(const float* __restrict__ cur, int wslot, const float* __restrict__ gb,
       const float* __restrict__ det, float* __restrict__ dstcur,
       float* __restrict__ outdet)
{
    extern __shared__ float smem[];
    float* xs  = smem;            // 64*72, gl = l0-3+m
    float* xso = smem + 4608;
    float* ds  = smem + 9216;     // 64*66 (stride 66)

    int b  = blockIdx.y;
    int l0 = blockIdx.x*64;
    int tid = threadIdx.x;
    const float* cb = cur + (size_t)b*C*L;

    for (int idx = tid; idx < 4608; idx += 256){
        int row = idx/72, m = idx - row*72;
        int gl = l0 - 3 + m;
        float v = (m < 70 && gl >= 0 && gl < 2048) ? cb[row*2048 + gl] : 0.f;
        xs[idx] = v;
        if (m > 0) xso[row*72 + m - 1] = v;
        else       xso[row*72 + 71] = 0.f;
    }
    for (int idx = tid; idx < 4096; idx += 256){
        int row = idx >> 6, q = idx & 63;
        ds[row*66 + q] = det[((size_t)b*64 + row)*2048 + l0 + q];
    }
    __syncthreads();

    int o = tid & 63, seg = tid >> 6;
    int k0 = seg*8;
    const float4* W = ((const float4*)g_W4s) + (size_t)wslot*4096;
    ull acc[8];
    #pragma unroll
    for (int k = 0; k < 8; k++) acc[k] = 0ull;
    {
        float4 wnext = W[o];
        for (int i = 0; i < 64; i++){
            float4 wv = wnext;
            wnext = W[(((i+1)&63)<<6) + o];
            ull w0 = pk2(wv.x), w1 = pk2(wv.y), w2 = pk2(wv.z);
            const ull* A = (const ull*)(xs  + i*72) + (k0 + 1);
            const ull* O = (const ull*)(xso + i*72) + (k0 + 1);
            ull Ep = A[0];
            #pragma unroll
            for (int k = 0; k < 8; k++){
                ull En = A[k+1];
                ull Ok = O[k];
                acc[k] = fma2(w0, Ep, acc[k]);
                acc[k] = fma2(w1, Ok, acc[k]);
                acc[k] = fma2(w2, En, acc[k]);
                Ep = En;
            }
        }
    }
    {
        float gbv = gb[o];
        size_t rowbase = ((size_t)b*64 + o)*2048 + l0;
        #pragma unroll
        for (int k = 0; k < 8; k++){
            int jq = 2*(k0 + k);
            float lo, hi; upk(acc[k], lo, hi);
            float g0 = sigmf(lo + gbv), g1 = sigmf(hi + gbv);
            float cv0 = xs[o*72 + jq + 3];
            float cv1 = xs[o*72 + jq + 4];
            float d0 = ds[o*66 + jq];
            float d1 = ds[o*66 + jq + 1];
            *(ull*)(dstcur + rowbase + jq) = mk2(cv0 + g0*d0, cv1 + g1*d1);
        }
    }
    if (outdet){
        for (int idx = tid; idx < 4096; idx += 256){
            int row = idx >> 6, q = idx & 63;
            outdet[((size_t)b*64 + row)*2048 + l0 + q] = ds[row*66 + q];
        }
    }
}

// ---------------- 1x1 attention (C->16->C) + detail modulation ----------------
__global__ void k_attn(const float* __restrict__ cur,
                       const float* __restrict__ w1, const float* __restrict__ b1,
                       const float* __restrict__ w2, const float* __restrict__ b2,
                       const float* __restrict__ det, float* __restrict__ dmod,
                       float* __restrict__ outdet){
    __shared__ float sm[128*65];
    int b = blockIdx.y, l0 = blockIdx.x*128;
    int tid = threadIdx.x;
    for (int idx = tid; idx < 64*128; idx += 128){
        int c = idx >> 7, l = idx & 127;
        sm[l*65 + c] = cur[((size_t)b*64+c)*2048 + l0 + l];
    }
    __syncthreads();
    int l = tid;
    float h16[16];
    #pragma unroll
    for (int k = 0; k < 16; k++){
        float a = b1[k];
        const float* wr = w1 + k*64;
        #pragma unroll 8
        for (int c = 0; c < 64; c++) a += wr[c]*sm[l*65+c];
        h16[k] = geluf(a);
    }
    for (int c = 0; c < 64; c++){
        float a = b2[c];
        const float* wr = w2 + c*16;
        #pragma unroll
        for (int k = 0; k < 16; k++) a += wr[k]*h16[k];
        a = sigmf(a);
        size_t id = ((size_t)b*64+c)*2048 + l0 + l;
        float dv = det[id]*(1.f + a);
        dmod[id] = dv;
        outdet[id] = dv;
    }
}

__global__ void k_tail(float* out){ out[NOUT] = g_ortho[0]; }

// ---------------- host ----------------
extern "C" void kernel_launch(void* const* d_in, const int* in_sizes, int n_in,
                              void* d_out, int out_size) {
    const float* x      = (const float*)d_in[0];
    const float* dy_w1  = (const float*)d_in[1];
    const float* dy_b1  = (const float*)d_in[2];
    const float* dy_wg1 = (const float*)d_in[3];
    const float* dy_bg1 = (const float*)d_in[4];
    const float* dy_wg2 = (const float*)d_in[5];
    const float* dy_bg2 = (const float*)d_in[6];
    const float* c1w    = (const float*)d_in[7];
    const float* c1b    = (const float*)d_in[8];
    const float* c2w    = (const float*)d_in[9];
    const float* c2b    = (const float*)d_in[10];
    const float* wt     = (const float*)d_in[11];
    const float* bt     = (const float*)d_in[12];
    const float* wm     = (const float*)d_in[13];
    const float* bm     = (const float*)d_in[14];
    const float* emb    = (const float*)d_in[15];
    const float* gate_w = (const float*)d_in[16];
    const float* gate_b = (const float*)d_in[17];
    const float* a1w    = (const float*)d_in[18];
    const float* a1b    = (const float*)d_in[19];
    const float* a2w    = (const float*)d_in[20];
    const float* a2b    = (const float*)d_in[21];
    float* out = (float*)d_out;

    cudaFuncSetAttribute(k_stage, cudaFuncAttributeMaxDynamicSharedMemorySize, 37376);
    cudaFuncSetAttribute(k_gate,  cudaFuncAttributeMaxDynamicSharedMemorySize, 53760);

    void* pbig = nullptr; cudaGetSymbolAddress(&pbig, g_big);
    float* big = (float*)pbig;

    float* bufA = big + (size_t)S_BUFA*BCL;
    float* bufB = big + (size_t)S_BUFB*BCL;
    float* detb = big + (size_t)S_DET*BCL;
    float* evob = big + (size_t)S_EVO*BCL;
    float* curA = big + (size_t)S_CURA*BCL;
    float* curB = big + (size_t)S_CURB*BCL;
    float* dmod = big + (size_t)S_DMOD*BCL;

    k_pack<<<176,256>>>(c1w, c2w, gate_w);

    // ---- decomposition (3 levels); final approx lands in bufA ----
    const float* aps[3] = { x, bufA, bufB };
    float* naps[3] = { bufA, bufB, bufA };
    for (int lev = 0; lev < 3; lev++){
        k_stat<<<512,256>>>(aps[lev]);
        k_mlp<<<1,256>>>(dy_w1, dy_b1, dy_wg1, dy_bg1, dy_wg2, dy_bg2);
        k_filt<<<4096,256>>>(aps[lev], naps[lev], detb + (size_t)lev*BCL);
    }

    // ---- ODE prep for all 4 levels ----
    k_init<<<1,32>>>();
    k_grid1<<<2048,256>>>();
    k_grid2<<<4,256>>>();
    k_mod<<<32,256>>>(wt, bt, wm, bm, emb);
    k_energyB<<<32,256>>>(0);

    // ---- RK4: 16 fused stages, all levels concurrently ----
    dim3 sgrid(32, 8, 4);
    for (int j = 0; j < 4; j++)
        for (int s = 0; s < 4; s++)
            k_stage<<<sgrid, 256, 37376>>>(c1b, c2b, j, s);

    k_energyB<<<32,256>>>(32);
    k_scale<<<4096,256>>>();

    // ---- reconstruction ----
    dim3 ggrid(32, 8);
    dim3 agrid(16, 8);
    k_gate<<<ggrid,256,53760>>>(curA, 10, gate_b + 128,
                                evob + (size_t)2*BCL, curB, out + (size_t)3*BCL);
    k_attn<<<agrid,128>>>(curB, a1w + 1024, a1b + 16, a2w + 1024, a2b + 64,
                          evob + (size_t)1*BCL, dmod, out + (size_t)2*BCL);
    k_gate<<<ggrid,256,53760>>>(curB, 9, gate_b + 64, dmod, curA, nullptr);
    k_attn<<<agrid,128>>>(curA, a1w, a1b, a2w, a2b,
                          evob, dmod, out + (size_t)1*BCL);
    k_gate<<<ggrid,256,53760>>>(curA, 8, gate_b, dmod, out, nullptr);

    if (out_size > NOUT) k_tail<<<1,1>>>(out);
}

// round 14
// speedup vs baseline: 1.2015x; 1.0031x over previous
#include <cuda_runtime.h>
#include <math.h>

#define B 8
#define C 64
#define L 2048
#define BCL (B*C*L)          // 1048576
#define NOUT (4*BCL)

// buffer slots in g_big
#define S_BUFA 0
#define S_BUFB 1
#define S_DET  2   // 3 buffers (lvl 1..3 coeffs; double as y state)
#define S_YIN  5   // 4
#define S_ACC  9   // 4
#define S_EVO  13  // 3
#define S_CURA 16
#define S_CURB 17
#define S_DMOD 18
#define NBUF   19

typedef unsigned long long ull;

// ---------------- device scratch (no allocation) ----------------
__device__ float g_big[(size_t)NBUF*BCL];
__device__ float g_W4s[11*4096*4];    // packed conv weights (float4 per (i,o))
__device__ float g_stat[512];
__device__ float g_lo[56], g_hi[56];
__device__ float g_ortho[1];
__device__ float g_ts[24];            // [lvl][5]
__device__ float g_rows[4*2048];
__device__ float g_modb[4*16*128];
__device__ float g_energy[64];
__device__ unsigned g_mm[8];

// ---------------- helpers ----------------
__device__ __forceinline__ float geluf(float x){ return 0.5f*x*(1.f+erff(x*0.70710678118654752f)); }
__device__ __forceinline__ float siluf(float x){ return x/(1.f+expf(-x)); }
__device__ __forceinline__ float sigmf(float x){ return 1.f/(1.f+expf(-x)); }

__device__ __forceinline__ ull pk2(float v){
    ull r; asm("mov.b64 %0,{%1,%1};" : "=l"(r) : "f"(v)); return r;
}
__device__ __forceinline__ ull mk2(float lo, float hi){
    ull r; asm("mov.b64 %0,{%1,%2};" : "=l"(r) : "f"(lo), "f"(hi)); return r;
}
__device__ __forceinline__ void upk(ull v, float& lo, float& hi){
    asm("mov.b64 {%0,%1},%2;" : "=f"(lo), "=f"(hi) : "l"(v));
}
__device__ __forceinline__ ull fma2(ull a, ull b, ull c){
    ull d; asm("fma.rn.f32x2 %0,%1,%2,%3;" : "=l"(d) : "l"(a), "l"(b), "l"(c)); return d;
}
// odd pair from two even pairs: (a.hi, b.lo)
__device__ __forceinline__ ull mkO(ull a, ull b){
    float alo, ahi, blo, bhi; upk(a, alo, ahi); upk(b, blo, bhi);
    return mk2(ahi, blo);
}

__device__ __forceinline__ size_t yboff(int lvl){
    return (lvl == 0) ? (size_t)S_BUFA*BCL : (size_t)(S_DET+lvl-1)*BCL;
}

// ---------------- pack conv weights [o][i][3] -> float4[i*64+o] ----------------
__global__ void k_pack(const float* __restrict__ c1, const float* __restrict__ c2,
                       const float* __restrict__ gw){
    int idx = blockIdx.x*256 + threadIdx.x;
    if (idx >= 11*4096) return;
    int slot = idx >> 12; int r = idx & 4095; int o = r >> 6; int i = r & 63;
    const float* src;
    if (slot < 4)      src = c1 + slot*12288;
    else if (slot < 8) src = c2 + (slot-4)*12288;
    else               src = gw + (slot-8)*12288;
    const float* w = src + (o*64 + i)*3;
    ((float4*)g_W4s)[slot*4096 + i*64 + o] = make_float4(w[0], w[1], w[2], 0.f);
}

// ---------------- stat: mean over L ----------------
__global__ void k_stat(const float* __restrict__ src){
    int r = blockIdx.x;
    const float* p = src + (size_t)r*L;
    float s = 0.f;
    for (int i = threadIdx.x; i < L; i += 256) s += p[i];
    __shared__ float red[256];
    red[threadIdx.x] = s; __syncthreads();
    for (int o = 128; o > 0; o >>= 1){
        if (threadIdx.x < o) red[threadIdx.x] += red[threadIdx.x+o];
        __syncthreads();
    }
    if (threadIdx.x == 0) g_stat[r] = red[0]*(1.f/(float)L);
}

// ---------------- dywan MLP + ortho (single block) ----------------
__global__ void k_mlp(const float* __restrict__ w1, const float* __restrict__ b1,
                      const float* __restrict__ wg1, const float* __restrict__ bg1,
                      const float* __restrict__ wg2, const float* __restrict__ bg2){
    __shared__ float ss[512], h1[512], h2[1024], sf[112];
    int tid = threadIdx.x;
    for (int i = tid; i < 512; i += 256) ss[i] = g_stat[i];
    __syncthreads();
    for (int idx = tid; idx < 512; idx += 256){
        int b = idx >> 6, j = idx & 63;
        float s = b1[j];
        const float* w = w1 + j*64; const float* st = ss + b*64;
        #pragma unroll 8
        for (int c = 0; c < 64; c++) s += w[c]*st[c];
        h1[idx] = geluf(s);
    }
    __syncthreads();
    for (int idx = tid; idx < 1024; idx += 256){
        int b = idx >> 7, j = idx & 127;
        float s = bg1[j];
        const float* w = wg1 + j*64; const float* hh = h1 + b*64;
        #pragma unroll 8
        for (int c = 0; c < 64; c++) s += w[c]*hh[c];
        h2[idx] = geluf(s);
    }
    __syncthreads();
    if (tid < 112){
        int b = tid/14, j = tid%14;
        float s = bg2[j];
        const float* w = wg2 + j*128; const float* hh = h2 + b*128;
        #pragma unroll 8
        for (int c = 0; c < 128; c++) s += w[c]*hh[c];
        sf[b*14+j] = s;
        if (j < 7) g_lo[b*7+j] = s; else g_hi[b*7+(j-7)] = s;
    }
    __syncthreads();
    if (tid == 0){
        float sm = 0.f;
        for (int b = 0; b < 8; b++){
            float prev = 0.f;
            for (int i = 0; i < 7; i++){ float v = sf[b*14+i]; sm += fabsf(v-prev); prev = v; }
            sm += fabsf(prev);
        }
        float lo_smooth = sm/64.f;
        float lon[8][7];
        for (int b = 0; b < 8; b++){
            float n = 0.f;
            for (int i = 0; i < 7; i++){ float v = sf[b*14+i]; n += v*v; }
            n = sqrtf(n) + 1e-8f;
            for (int i = 0; i < 7; i++) lon[b][i] = sf[b*14+i]/n;
        }
        float shift = 0.f;
        for (int s = 1; s <= 3; s++){
            float t = 0.f;
            for (int b = 0; b < 8; b++)
                for (int i = 0; i < 7; i++)
                    for (int jj = 0; jj < 7; jj++)
                        t += fabsf(lon[b][i]*lon[b][(jj - s + 7)%7]);
            shift += t/(8.f*49.f);
        }
        float amp = 0.f;
        for (int b = 0; b < 8; b++){
            float q = 0.f;
            for (int i = 0; i < 7; i++) q += lon[b][i]*lon[b][i];
            amp += fabsf(q - 1.f);
        }
        amp /= 8.f;
        g_ortho[0] = 0.01f*(shift+amp) + 0.1f*lo_smooth;
    }
}

// ---------------- per-batch 7-tap filter (edge pad), both filters ----------------
__global__ void k_filt(const float* __restrict__ src, float* __restrict__ na,
                       float* __restrict__ det){
    int idx = blockIdx.x*256 + threadIdx.x;
    if (idx >= BCL) return;
    int l = idx & (L-1);
    int bc = idx >> 11;
    int b = bc >> 6;
    const float* p = src + (size_t)bc*L;
    const float* flo = g_lo + b*7; const float* fhi = g_hi + b*7;
    float sa = 0.f, sd = 0.f;
    #pragma unroll
    for (int t = 0; t < 7; t++){
        int m = l + t - 3; m = m < 0 ? 0 : (m > L-1 ? L-1 : m);
        float v = p[m];
        sa += v*flo[t]; sd += v*fhi[t];
    }
    na[idx] = sa; det[idx] = sd;
}

__global__ void k_init(){
    int t = threadIdx.x;
    if (t < 4){ g_mm[t*2] = 0x7f7fffffu; g_mm[t*2+1] = 0u; }
}

// ---------------- adaptive time grid pass 1 (batched over 4 levels) ----------------
__global__ void k_grid1(){
    __shared__ float sd[2048];
    __shared__ float R[6][256];
    int lvl = blockIdx.x >> 9;
    int r = blockIdx.x & 511;
    const float* p = g_big + yboff(lvl) + (size_t)r*2048;
    int t = threadIdx.x;
    for (int i = t; i < 2048; i += 256) sd[i] = p[i];
    __syncthreads();
    float s1=0.f,s2=0.f,s3=0.f,s4=0.f, mn=3.4e38f, mx=0.f;
    for (int jj = t; jj < 2047; jj += 256){
        int lo = jj-2; if (lo < 0) lo = 0;
        int hi = jj+2; if (hi > 2046) hi = 2046;
        float g = 0.f;
        for (int q = lo; q <= hi; q++) g += fabsf(sd[q+1]-sd[q]);
        float inten = g*0.2f;
        mn = fminf(mn, inten); mx = fmaxf(mx, inten);
        if (jj < 511)  s1 += inten;
        if (jj < 1023) s2 += inten;
        if (jj < 1534) s3 += inten;
        if (jj < 2046) s4 += inten;
    }
    R[0][t]=s1; R[1][t]=s2; R[2][t]=s3; R[3][t]=s4; R[4][t]=mn; R[5][t]=mx;
    __syncthreads();
    for (int o = 128; o > 0; o >>= 1){
        if (t < o){
            R[0][t]+=R[0][t+o]; R[1][t]+=R[1][t+o]; R[2][t]+=R[2][t+o]; R[3][t]+=R[3][t+o];
            R[4][t]=fminf(R[4][t],R[4][t+o]); R[5][t]=fmaxf(R[5][t],R[5][t+o]);
        }
        __syncthreads();
    }
    if (t == 0){
        float* rows = g_rows + lvl*2048;
        rows[r*4+0]=R[0][0]; rows[r*4+1]=R[1][0]; rows[r*4+2]=R[2][0]; rows[r*4+3]=R[3][0];
        atomicMin(&g_mm[lvl*2+0], __float_as_uint(R[4][0]));
        atomicMax(&g_mm[lvl*2+1], __float_as_uint(R[5][0]));
    }
}

// ---------------- grid pass 2 (one block per level) ----------------
__global__ void k_grid2(){
    __shared__ float R[5][256];
    int lvl = blockIdx.x;
    float mn = __uint_as_float(g_mm[lvl*2+0]);
    float mx = __uint_as_float(g_mm[lvl*2+1]);
    float a, bb;
    if (mx - mn < 1e-8f){ a = 0.f; bb = 0.5f; }
    else { a = 0.9f/(mx - mn + 1e-30f); bb = 0.1f - a*mn; }
    int t = threadIdx.x;
    const float* rows = g_rows + lvl*2048;
    float p1=0.f,p2=0.f,p3=0.f,p4=0.f,m=-1.f;
    for (int r = t; r < 512; r += 256){
        float t1 = a*rows[r*4+0] + bb*511.f;
        float t2 = a*rows[r*4+1] + bb*1023.f;
        float t3 = a*rows[r*4+2] + bb*1534.f;
        float t4 = a*rows[r*4+3] + bb*2046.f;
        p1+=t1; p2+=t2; p3+=t3; p4+=t4; m = fmaxf(m, t4);
    }
    R[0][t]=p1; R[1][t]=p2; R[2][t]=p3; R[3][t]=p4; R[4][t]=m;
    __syncthreads();
    for (int o = 128; o > 0; o >>= 1){
        if (t < o){
            R[0][t]+=R[0][t+o]; R[1][t]+=R[1][t+o]; R[2][t]+=R[2][t+o]; R[3][t]+=R[3][t+o];
            R[4][t]=fmaxf(R[4][t],R[4][t+o]);
        }
        __syncthreads();
    }
    if (t == 0){
        float M = fmaxf(R[4][0], 1e-12f);
        float inv = 1.f/(512.f*M);
        float* ts = g_ts + lvl*5;
        ts[0]=0.f; ts[1]=R[0][0]*inv; ts[2]=R[1][0]*inv; ts[3]=R[2][0]*inv; ts[4]=R[3][0]*inv;
    }
}

// ---------------- modulation table (batched over levels) ----------------
__global__ void k_mod(const float* __restrict__ wt, const float* __restrict__ bt,
                      const float* __restrict__ wm, const float* __restrict__ bm,
                      const float* __restrict__ emb){
    int gid = blockIdx.x*256 + threadIdx.x;
    if (gid >= 8192) return;
    int lvl = gid >> 11; int rem = gid & 2047;
    int js = rem >> 7; int r = rem & 127;
    int j = js >> 2, s = js & 3;
    float t0 = g_ts[lvl*5+j], t1 = g_ts[lvl*5+j+1];
    float t = (s == 0) ? t0 : (s == 3 ? t1 : t0 + 0.5f*(t1-t0));
    float acc = bm[lvl*128 + r];
    #pragma unroll
    for (int k = 0; k < 16; k++){
        float te = siluf(wt[lvl*16+k]*t + bt[lvl*16+k]);
        acc = fmaf(wm[(lvl*128+r)*16+k], te, acc);
    }
    if (r < 64) g_modb[(lvl*16+js)*128 + r] = 1.f + acc + emb[(lvl*8+lvl)*64 + r];
    else        g_modb[(lvl*16+js)*128 + 64 + (r-64)] = acc;
}

// ---------------- energy: per (lvl,b) mean of squares ----------------
__global__ void k_energyB(int off){
    int lvl = blockIdx.x >> 3, b = blockIdx.x & 7;
    const float* p = g_big + yboff(lvl) + (size_t)b*131072;
    double s = 0.0;
    for (int i = threadIdx.x; i < 131072; i += 256){ float v = p[i]; s += (double)v*(double)v; }
    __shared__ double red[256];
    red[threadIdx.x] = s; __syncthreads();
    for (int o = 128; o > 0; o >>= 1){
        if (threadIdx.x < o) red[threadIdx.x] += red[threadIdx.x+o];
        __syncthreads();
    }
    if (threadIdx.x == 0) g_energy[off + lvl*8 + b] = (float)(red[0]/131072.0);
}

__global__ void k_scale(){
    int idx = blockIdx.x*256 + threadIdx.x;
    if (idx >= 4*(BCL/4)) return;
    int lvl = idx >> 18;
    int r = idx & (BCL/4 - 1);
    int b = r >> 15;
    float sc = sqrtf(g_energy[lvl*8+b]/(g_energy[32+lvl*8+b]+1e-8f));
    const float4* src = (const float4*)(g_big + yboff(lvl));
    float4* dst = (float4*)(g_big + ((lvl == 0) ? (size_t)S_CURA*BCL : (size_t)(S_EVO+lvl-1)*BCL));
    float4 v = src[r];
    v.x*=sc; v.y*=sc; v.z*=sc; v.w*=sc;
    dst[r] = v;
}

// ---------------- fused RK4 stage (lean core, no shadow arrays, 4 CTAs/SM) ----------------
// grid (32 ltiles(64 cols), 8 batch, 4 levels), 256 threads
// smem: xs 64x72 (cols gl=l0-3+m, m<70 valid), hs 64x74 (cols ghl=l0-2+hc). 37376 B.
__global__ void __launch_bounds__(256,4)
k_stage(const float* __restrict__ c1b, const float* __restrict__ c2b, int j, int s)
{
    extern __shared__ float smem[];
    float* xs = smem;            // 64*72
    float* hs = smem + 4608;     // 64*74

    int lvl = blockIdx.z;
    int b   = blockIdx.y;
    int l0  = blockIdx.x*64;
    int tid = threadIdx.x;

    size_t ybo = yboff(lvl);
    size_t lvlbcl = (size_t)lvl*BCL;
    const float* cin = g_big + ((s==0) ? ybo : ((size_t)S_YIN*BCL + lvlbcl)) + (size_t)b*C*L;

    for (int idx = tid; idx < 4608; idx += 256){
        int row = idx/72, m = idx - row*72;
        int gl = l0 - 3 + m;
        xs[idx] = (m < 70 && gl >= 0 && gl < 2048) ? cin[row*2048 + gl] : 0.f;
    }
    __syncthreads();

    int o = tid & 63, seg = tid >> 6;
    const float4* W1 = ((const float4*)g_W4s) + (size_t)lvl*4096;
    const float4* W2 = ((const float4*)g_W4s) + (size_t)(4+lvl)*4096;

    // ---- phase 1: conv1 -> h pairs p = seg*9 .. seg*9+8 ----
    // Hpair[p] = w0*E[p] + w1*O[p] + w2*E[p+1];  O[p] = (E[p].hi, E[p+1].lo)
    int p0 = seg*9;
    ull acc1[9];
    #pragma unroll
    for (int k = 0; k < 9; k++) acc1[k] = 0ull;
    {
        float4 wnext = W1[o];
        for (int i = 0; i < 64; i++){
            float4 wv = wnext;
            wnext = W1[(((i+1)&63)<<6) + o];
            ull w0 = pk2(wv.x), w1 = pk2(wv.y), w2 = pk2(wv.z);
            const ull* A = (const ull*)(xs + i*72) + p0;
            ull Ep = A[0];
            #pragma unroll
            for (int k = 0; k < 9; k++){
                ull En = A[k+1];
                ull Ok = mkO(Ep, En);
                acc1[k] = fma2(w0, Ep, acc1[k]);
                acc1[k] = fma2(w1, Ok, acc1[k]);
                acc1[k] = fma2(w2, En, acc1[k]);
                Ep = En;
            }
        }
    }
    {
        float b1v = c1b[lvl*64 + o];
        #pragma unroll
        for (int k = 0; k < 9; k++){
            int p = p0 + k;
            int g0 = l0 - 2 + 2*p;
            float lo, hi; upk(acc1[k], lo, hi);
            float h0 = (g0   >= 0 && g0   < 2048) ? geluf(lo + b1v) : 0.f;
            float h1 = (g0+1 >= 0 && g0+1 < 2048) ? geluf(hi + b1v) : 0.f;
            *(ull*)(hs + o*74 + 2*p) = mk2(h0, h1);
        }
    }
    __syncthreads();

    // ---- phase 2: conv2, out pairs op = seg*8 .. seg*8+7 ----
    // OutPair[op] = w0*HO[op] + w1*HE[op+1] + w2*HO[op+1];  HO[p] = (HE[p].hi, HE[p+1].lo)
    int op0 = seg*8;
    ull acc2[8];
    #pragma unroll
    for (int k = 0; k < 8; k++) acc2[k] = 0ull;
    {
        float4 wnext = W2[o];
        for (int i = 0; i < 64; i++){
            float4 wv = wnext;
            wnext = W2[(((i+1)&63)<<6) + o];
            ull w0 = pk2(wv.x), w1 = pk2(wv.y), w2 = pk2(wv.z);
            const ull* H = (const ull*)(hs + i*74) + op0;
            ull E1 = H[0];
            ull E2 = H[1];
            ull Op = mkO(E1, E2);
            E1 = E2;
            #pragma unroll
            for (int k = 0; k < 8; k++){
                ull En = H[k+2];
                ull On = mkO(E1, En);
                acc2[k] = fma2(w0, Op, acc2[k]);
                acc2[k] = fma2(w1, E1, acc2[k]);
                acc2[k] = fma2(w2, On, acc2[k]);
                Op = On; E1 = En;
            }
        }
    }

    // ---- epilogue: kv = silu(mod) - 0.1*y_stage ----
    float kv[8][2];
    {
        int msel = (lvl*16 + j*4 + s)*128;
        float m1p = g_modb[msel + o];
        float bet = g_modb[msel + 64 + o];
        float b2v = c2b[lvl*64 + o];
        #pragma unroll
        for (int k = 0; k < 8; k++){
            int col = 2*(op0 + k);
            float lo, hi; upk(acc2[k], lo, hi);
            kv[k][0] = siluf((lo + b2v)*m1p + bet) - 0.1f*xs[o*72 + col + 3];
            kv[k][1] = siluf((hi + b2v)*m1p + bet) - 0.1f*xs[o*72 + col + 4];
        }
    }
    __syncthreads();
    #pragma unroll
    for (int k = 0; k < 8; k++){
        int col = 2*(op0 + k);
        *(ull*)(hs + o*74 + col) = mk2(kv[k][0], kv[k][1]);
    }
    __syncthreads();

    float dt  = g_ts[lvl*5 + j + 1] - g_ts[lvl*5 + j];
    float c_acc = (s == 0 || s == 3) ? dt*(1.f/6.f) : dt*(1.f/3.f);
    float c_y   = (s == 2) ? dt : dt*0.5f;
    for (int idx = tid; idx < 4096; idx += 256){
        int o2 = idx >> 6, q = idx & 63;
        float kvv = hs[o2*74 + q];
        size_t g = ((size_t)b*64 + o2)*2048 + l0 + q;
        if (s == 0){
            float yvv = g_big[ybo + g];
            g_big[(size_t)S_ACC*BCL + lvlbcl + g] = yvv + c_acc*kvv;
            g_big[(size_t)S_YIN*BCL + lvlbcl + g] = yvv + c_y*kvv;
        } else if (s < 3){
            float yvv = g_big[ybo + g];
            g_big[(size_t)S_ACC*BCL + lvlbcl + g] += c_acc*kvv;
            g_big[(size_t)S_YIN*BCL + lvlbcl + g] = yvv + c_y*kvv;
        } else {
            g_big[ybo + g] = g_big[(size_t)S_ACC*BCL + lvlbcl + g] + c_acc*kvv;
        }
    }
}

// ---------------- recon gate conv (packed core): dst = cur + sigmoid(conv(cur)+gb)*det ----
// grid (32 ltiles, 8 batch), 256 threads. smem: xs 4608 + xso 4608 + ds 64*66
__global__ void __launch_bounds__(256,3)
k_gate(const float* __restrict__ cur, int wslot, const float* __restrict__ gb,
       const float* __restrict__ det, float* __restrict__ dstcur,
       float* __restrict__ outdet)
{
    extern __shared__ float smem[];
    float* xs  = smem;            // 64*72, gl = l0-3+m
    float* xso = smem + 4608;
    float* ds  = smem + 9216;     // 64*66 (stride 66)

    int b  = blockIdx.y;
    int l0 = blockIdx.x*64;
    int tid = threadIdx.x;
    const float* cb = cur + (size_t)b*C*L;

    for (int idx = tid; idx < 4608; idx += 256){
        int row = idx/72, m = idx - row*72;
        int gl = l0 - 3 + m;
        float v = (m < 70 && gl >= 0 && gl < 2048) ? cb[row*2048 + gl] : 0.f;
        xs[idx] = v;
        if (m > 0) xso[row*72 + m - 1] = v;
        else       xso[row*72 + 71] = 0.f;
    }
    for (int idx = tid; idx < 4096; idx += 256){
        int row = idx >> 6, q = idx & 63;
        ds[row*66 + q] = det[((size_t)b*64 + row)*2048 + l0 + q];
    }
    __syncthreads();

    int o = tid & 63, seg = tid >> 6;
    int k0 = seg*8;
    const float4* W = ((const float4*)g_W4s) + (size_t)wslot*4096;
    ull acc[8];
    #pragma unroll
    for (int k = 0; k < 8; k++) acc[k] = 0ull;
    {
        float4 wnext = W[o];
        for (int i = 0; i < 64; i++){
            float4 wv = wnext;
            wnext = W[(((i+1)&63)<<6) + o];
            ull w0 = pk2(wv.x), w1 = pk2(wv.y), w2 = pk2(wv.z);
            const ull* A = (const ull*)(xs  + i*72) + (k0 + 1);
            const ull* O = (const ull*)(xso + i*72) + (k0 + 1);
            ull Ep = A[0];
            #pragma unroll
            for (int k = 0; k < 8; k++){
                ull En = A[k+1];
                ull Ok = O[k];
                acc[k] = fma2(w0, Ep, acc[k]);
                acc[k] = fma2(w1, Ok, acc[k]);
                acc[k] = fma2(w2, En, acc[k]);
                Ep = En;
            }
        }
    }
    {
        float gbv = gb[o];
        size_t rowbase = ((size_t)b*64 + o)*2048 + l0;
        #pragma unroll
        for (int k = 0; k < 8; k++){
            int jq = 2*(k0 + k);
            float lo, hi; upk(acc[k], lo, hi);
            float g0 = sigmf(lo + gbv), g1 = sigmf(hi + gbv);
            float cv0 = xs[o*72 + jq + 3];
            float cv1 = xs[o*72 + jq + 4];
            float d0 = ds[o*66 + jq];
            float d1 = ds[o*66 + jq + 1];
            *(ull*)(dstcur + rowbase + jq) = mk2(cv0 + g0*d0, cv1 + g1*d1);
        }
    }
    if (outdet){
        for (int idx = tid; idx < 4096; idx += 256){
            int row = idx >> 6, q = idx & 63;
            outdet[((size_t)b*64 + row)*2048 + l0 + q] = ds[row*66 + q];
        }
    }
}

// ---------------- 1x1 attention (C->16->C) + detail modulation ----------------
__global__ void k_attn(const float* __restrict__ cur,
                       const float* __restrict__ w1, const float* __restrict__ b1,
                       const float* __restrict__ w2, const float* __restrict__ b2,
                       const float* __restrict__ det, float* __restrict__ dmod,
                       float* __restrict__ outdet){
    __shared__ float sm[128*65];
    int b = blockIdx.y, l0 = blockIdx.x*128;
    int tid = threadIdx.x;
    for (int idx = tid; idx < 64*128; idx += 128){
        int c = idx >> 7, l = idx & 127;
        sm[l*65 + c] = cur[((size_t)b*64+c)*2048 + l0 + l];
    }
    __syncthreads();
    int l = tid;
    float h16[16];
    #pragma unroll
    for (int k = 0; k < 16; k++){
        float a = b1[k];
        const float* wr = w1 + k*64;
        #pragma unroll 8
        for (int c = 0; c < 64; c++) a += wr[c]*sm[l*65+c];
        h16[k] = geluf(a);
    }
    for (int c = 0; c < 64; c++){
        float a = b2[c];
        const float* wr = w2 + c*16;
        #pragma unroll
        for (int k = 0; k < 16; k++) a += wr[k]*h16[k];
        a = sigmf(a);
        size_t id = ((size_t)b*64+c)*2048 + l0 + l;
        float dv = det[id]*(1.f + a);
        dmod[id] = dv;
        outdet[id] = dv;
    }
}

__global__ void k_tail(float* out){ out[NOUT] = g_ortho[0]; }

// ---------------- host ----------------
extern "C" void kernel_launch(void* const* d_in, const int* in_sizes, int n_in,
                              void* d_out, int out_size) {
    const float* x      = (const float*)d_in[0];
    const float* dy_w1  = (const float*)d_in[1];
    const float* dy_b1  = (const float*)d_in[2];
    const float* dy_wg1 = (const float*)d_in[3];
    const float* dy_bg1 = (const float*)d_in[4];
    const float* dy_wg2 = (const float*)d_in[5];
    const float* dy_bg2 = (const float*)d_in[6];
    const float* c1w    = (const float*)d_in[7];
    const float* c1b    = (const float*)d_in[8];
    const float* c2w    = (const float*)d_in[9];
    const float* c2b    = (const float*)d_in[10];
    const float* wt     = (const float*)d_in[11];
    const float* bt     = (const float*)d_in[12];
    const float* wm     = (const float*)d_in[13];
    const float* bm     = (const float*)d_in[14];
    const float* emb    = (const float*)d_in[15];
    const float* gate_w = (const float*)d_in[16];
    const float* gate_b = (const float*)d_in[17];
    const float* a1w    = (const float*)d_in[18];
    const float* a1b    = (const float*)d_in[19];
    const float* a2w    = (const float*)d_in[20];
    const float* a2b    = (const float*)d_in[21];
    float* out = (float*)d_out;

    cudaFuncSetAttribute(k_stage, cudaFuncAttributeMaxDynamicSharedMemorySize, 37376);
    cudaFuncSetAttribute(k_gate,  cudaFuncAttributeMaxDynamicSharedMemorySize, 53760);

    void* pbig = nullptr; cudaGetSymbolAddress(&pbig, g_big);
    float* big = (float*)pbig;

    float* bufA = big + (size_t)S_BUFA*BCL;
    float* bufB = big + (size_t)S_BUFB*BCL;
    float* detb = big + (size_t)S_DET*BCL;
    float* evob = big + (size_t)S_EVO*BCL;
    float* curA = big + (size_t)S_CURA*BCL;
    float* curB = big + (size_t)S_CURB*BCL;
    float* dmod = big + (size_t)S_DMOD*BCL;

    k_pack<<<176,256>>>(c1w, c2w, gate_w);

    // ---- decomposition (3 levels); final approx lands in bufA ----
    const float* aps[3] = { x, bufA, bufB };
    float* naps[3] = { bufA, bufB, bufA };
    for (int lev = 0; lev < 3; lev++){
        k_stat<<<512,256>>>(aps[lev]);
        k_mlp<<<1,256>>>(dy_w1, dy_b1, dy_wg1, dy_bg1, dy_wg2, dy_bg2);
        k_filt<<<4096,256>>>(aps[lev], naps[lev], detb + (size_t)lev*BCL);
    }

    // ---- ODE prep for all 4 levels ----
    k_init<<<1,32>>>();
    k_grid1<<<2048,256>>>();
    k_grid2<<<4,256>>>();
    k_mod<<<32,256>>>(wt, bt, wm, bm, emb);
    k_energyB<<<32,256>>>(0);

    // ---- RK4: 16 fused stages, all levels concurrently ----
    dim3 sgrid(32, 8, 4);
    for (int j = 0; j < 4; j++)
        for (int s = 0; s < 4; s++)
            k_stage<<<sgrid, 256, 37376>>>(c1b, c2b, j, s);

    k_energyB<<<32,256>>>(32);
    k_scale<<<4096,256>>>();

    // ---- reconstruction ----
    dim3 ggrid(32, 8);
    dim3 agrid(16, 8);
    k_gate<<<ggrid,256,53760>>>(curA, 10, gate_b + 128,
                                evob + (size_t)2*BCL, curB, out + (size_t)3*BCL);
    k_attn<<<agrid,128>>>(curB, a1w + 1024, a1b + 16, a2w + 1024, a2b + 64,
                          evob + (size_t)1*BCL, dmod, out + (size_t)2*BCL);
    k_gate<<<ggrid,256,53760>>>(curB, 9, gate_b + 64, dmod, curA, nullptr);
    k_attn<<<agrid,128>>>(curA, a1w, a1b, a2w, a2b,
                          evob, dmod, out + (size_t)1*BCL);
    k_gate<<<ggrid,256,53760>>>(curA, 8, gate_b, dmod, out, nullptr);

    if (out_size > NOUT) k_tail<<<1,1>>>(out);
}